// round 13
// baseline (speedup 1.0000x reference)
#include <cuda_runtime.h>
#include <cuda_bf16.h>

#define QBINS    20
#define NWORD    6             // 24 byte-bins per array (bins 0..20 used, 21..23 pad)
#define ROWS     64
#define ROWLEN   1000000
#define ROWLEN4  (ROWLEN / 4)  // 250000 float4 per row
#define BPR      16            // blocks per row
#define NBLOCKS  (ROWS * BPR)  // 1024
#define CHUNK4   (ROWLEN4 / BPR)   // 15625 float4 per block
#define TPB      256
#define PITERS   31            // 31 * 2 * 256 = 15872 >= 15625

__device__ int g_part[ROWS][BPR][QBINS];
__device__ unsigned g_done;    // zero-init at load; last block resets each run

__device__ __forceinline__ int bin_of(float x) {
    // floor(fl_RN(20*x)) bit-exactly: RN(20x)+2^23 is an exact sum; RZ truncates.
    float y = __fadd_rz(__fmul_rn(x, 20.0f), 8388608.0f);  // 2^23
    return __float_as_int(y) - 0x4B000000;
}

// 8-bit packed bump: 4 bins per 32-bit word, bank = tid (conflict-free).
// Max increments per (thread, array) = 62 << 255, so bytes never overflow.
__device__ __forceinline__ void bump(int* __restrict__ h, int bin, int tid) {
    h[(bin >> 2) * TPB + tid] += 1 << ((bin & 3) << 3);
}

__global__ __launch_bounds__(TPB) void fused_kernel(const float* __restrict__ in,
                                                    float* __restrict__ out) {
    // Component-private sub-histograms: x->h0, y->h1, z->h2, w->h3.
    // Distinct arrays -> no alias hazard -> RMW chains are 2-deep, pipelinable.
    __shared__ int h0[NWORD * TPB];
    __shared__ int h1[NWORD * TPB];
    __shared__ int h2[NWORD * TPB];
    __shared__ int h3[NWORD * TPB];
    __shared__ int wsum[TPB / 32][QBINS];
    __shared__ float rowent[ROWS];
    __shared__ unsigned s_last;

    const int tid = threadIdx.x;
#pragma unroll
    for (int i = tid; i < NWORD * TPB; i += TPB) {
        h0[i] = 0; h1[i] = 0; h2[i] = 0; h3[i] = 0;
    }
    __syncthreads();

    const int row = blockIdx.x >> 4;
    const int blk = blockIdx.x & 15;
    const float4* __restrict__ p =
        (const float4*)(in + (size_t)row * ROWLEN) + (size_t)blk * CHUNK4;

    for (int k = 0; k < PITERS; k++) {
        int i0 = (2 * k) * TPB + tid;
        int i1 = i0 + TPB;
        float4 a = make_float4(1.0f, 1.0f, 1.0f, 1.0f);  // sentinel -> bin 20
        float4 b = make_float4(1.0f, 1.0f, 1.0f, 1.0f);
        if (i0 < CHUNK4) a = __ldcs(&p[i0]);
        if (i1 < CHUNK4) b = __ldcs(&p[i1]);

        bump(h0, bin_of(a.x), tid);
        bump(h1, bin_of(a.y), tid);
        bump(h2, bin_of(a.z), tid);
        bump(h3, bin_of(a.w), tid);
        bump(h0, bin_of(b.x), tid);
        bump(h1, bin_of(b.y), tid);
        bump(h2, bin_of(b.z), tid);
        bump(h3, bin_of(b.w), tid);
    }
    __syncthreads();

    // Block reduction: per bin sum 256 private byte-counters (bank = lane).
    const int wid  = tid >> 5;
    const int lane = tid & 31;
#pragma unroll
    for (int b = 0; b < QBINS; b++) {
        int idx = (b >> 2) * TPB + tid;
        int sh  = (b & 3) << 3;
        int v = ((h0[idx] >> sh) & 0xFF) + ((h1[idx] >> sh) & 0xFF)
              + ((h2[idx] >> sh) & 0xFF) + ((h3[idx] >> sh) & 0xFF);
        v = __reduce_add_sync(0xffffffffu, v);
        if (lane == 0) wsum[wid][b] = v;
    }
    __syncthreads();

    if (tid < QBINS) {
        int tot = 0;
#pragma unroll
        for (int w = 0; w < TPB / 32; w++) tot += wsum[w][tid];
        g_part[row][blk][tid] = tot;
    }

    // ---- last-block-done: entropy epilogue in the same launch ----
    __threadfence();
    if (tid == 0) s_last = (atomicAdd(&g_done, 1u) == NBLOCKS - 1u);
    __syncthreads();
    if (!s_last) return;

    if (tid == 0) g_done = 0u;   // reset for next graph replay (determinism)

    float ent = 0.0f;
    if (tid < ROWS) {
        const float invL = 1.0f / (float)ROWLEN;
#pragma unroll
        for (int b = 0; b < QBINS; b++) {
            int c = 0;
#pragma unroll
            for (int k = 0; k < BPR; k++) c += __ldcg(&g_part[tid][k][b]);
            if (c > 0) {
                float pr = (float)c * invL;
                ent -= pr * log2f(pr);
            }
        }
        rowent[tid] = ent;
    }
    __syncthreads();
    if (tid == 0) {
        float s = 0.0f;
#pragma unroll
        for (int r = 0; r < ROWS; r++) s += rowent[r];
        out[0] = s;
    }
}

extern "C" void kernel_launch(void* const* d_in, const int* in_sizes, int n_in,
                              void* d_out, int out_size) {
    (void)in_sizes; (void)n_in; (void)out_size;
    const float* in = (const float*)d_in[0];
    float* out = (float*)d_out;
    fused_kernel<<<NBLOCKS, TPB>>>(in, out);
}

// round 14
// speedup vs baseline: 1.5699x; 1.5699x over previous
#include <cuda_runtime.h>
#include <cuda_bf16.h>

#define QBINS    20
#define NPAIR    11            // packed: 2 bins per 32-bit word (16-bit halves)
#define ROWS     64
#define ROWLEN   1000000
#define ROWLEN4  (ROWLEN / 4)  // 250000 float4 per row
#define BPR      37            // blocks per row -> grid 2368 = 148 * 16 (2 full waves)
#define NBLOCKS  (ROWS * BPR)  // 2368
#define CHUNK4   ((ROWLEN4 + BPR - 1) / BPR)   // 6757
#define TPB      256
#define PITERS   ((CHUNK4 + 2 * TPB - 1) / (2 * TPB))  // 14

__device__ int g_part[ROWS][BPR][QBINS];
__device__ unsigned g_done;    // zero-init at load; last block resets each run

__device__ __forceinline__ int bin_of(float x) {
    // floor(fl_RN(20*x)) bit-exactly: RN(20x)+2^23 is an exact sum; RZ truncates.
    float y = __fadd_rz(__fmul_rn(x, 20.0f), 8388608.0f);  // 2^23
    return __float_as_int(y) - 0x4B000000;
}

// 16-bit packed bump, bank = tid (conflict-free). Max per half-counter:
// 14 iters * 4 bumps = 56 << 65535.
__device__ __forceinline__ void bump(int* h, int bin, int tid) {
    h[(bin >> 1) * TPB + tid] += 1 << ((bin & 1) << 4);
}

__global__ __launch_bounds__(TPB) void fused_kernel(const float* __restrict__ in,
                                                    float* __restrict__ out) {
    __shared__ int hA[NPAIR * TPB];
    __shared__ int hB[NPAIR * TPB];
    __shared__ int wsum[TPB / 32][QBINS];
    __shared__ float psum[TPB / 32];
    __shared__ unsigned s_last;

    const int tid = threadIdx.x;
#pragma unroll
    for (int i = tid; i < NPAIR * TPB; i += TPB) { hA[i] = 0; hB[i] = 0; }
    __syncthreads();

    const int row = blockIdx.x / BPR;
    const int blk = blockIdx.x - row * BPR;
    const int limit = min(CHUNK4, ROWLEN4 - blk * CHUNK4);  // short last chunk
    const float4* __restrict__ p =
        (const float4*)(in + (size_t)row * ROWLEN) + (size_t)blk * CHUNK4;

    for (int k = 0; k < PITERS; k++) {
        int i0 = (2 * k) * TPB + tid;
        int i1 = i0 + TPB;
        float4 a = make_float4(1.0f, 1.0f, 1.0f, 1.0f);  // sentinel -> bin 20
        float4 b = make_float4(1.0f, 1.0f, 1.0f, 1.0f);
        if (i0 < limit) a = __ldcs(&p[i0]);
        if (i1 < limit) b = __ldcs(&p[i1]);

        bump(hA, bin_of(a.x), tid);
        bump(hB, bin_of(a.z), tid);
        bump(hA, bin_of(a.y), tid);
        bump(hB, bin_of(a.w), tid);
        bump(hA, bin_of(b.x), tid);
        bump(hB, bin_of(b.z), tid);
        bump(hA, bin_of(b.y), tid);
        bump(hB, bin_of(b.w), tid);
    }
    __syncthreads();

    // Block reduction: per bin sum 256 private counters (bank = lane, conflict-free)
    const int wid  = tid >> 5;
    const int lane = tid & 31;
#pragma unroll
    for (int b = 0; b < QBINS; b++) {
        int wA = hA[(b >> 1) * TPB + tid];
        int wB = hB[(b >> 1) * TPB + tid];
        int sh = (b & 1) << 4;
        int v = ((wA >> sh) & 0xFFFF) + ((wB >> sh) & 0xFFFF);
        v = __reduce_add_sync(0xffffffffu, v);
        if (lane == 0) wsum[wid][b] = v;
    }
    __syncthreads();

    if (tid < QBINS) {
        int tot = 0;
#pragma unroll
        for (int w = 0; w < TPB / 32; w++) tot += wsum[w][tid];
        g_part[row][blk][tid] = tot;
    }

    // ---- last-block-done: entropy epilogue in the same launch ----
    __threadfence();
    if (tid == 0) s_last = (atomicAdd(&g_done, 1u) == NBLOCKS - 1u);
    __syncthreads();
    if (!s_last) return;

    if (tid == 0) g_done = 0u;   // reset for next graph replay (determinism)

    // Total loss = sum over all (row,bin) pairs of -p*log2(p).
    // 1280 pairs spread over 256 threads (5 each), 37 partials per pair.
    float ent = 0.0f;
    const float invL = 1.0f / (float)ROWLEN;
#pragma unroll
    for (int q = 0; q < (ROWS * QBINS) / TPB; q++) {
        int pair = q * TPB + tid;           // 0..1279
        int r = pair / QBINS;
        int b = pair - r * QBINS;
        int c = 0;
#pragma unroll
        for (int k = 0; k < BPR; k++) c += __ldcg(&g_part[r][k][b]);
        if (c > 0) {
            float pr = (float)c * invL;
            ent -= pr * log2f(pr);
        }
    }
    // block sum
#pragma unroll
    for (int o = 16; o > 0; o >>= 1) ent += __shfl_down_sync(0xffffffffu, ent, o);
    if (lane == 0) psum[wid] = ent;
    __syncthreads();
    if (tid == 0) {
        float s = 0.0f;
#pragma unroll
        for (int w = 0; w < TPB / 32; w++) s += psum[w];
        out[0] = s;
    }
}

extern "C" void kernel_launch(void* const* d_in, const int* in_sizes, int n_in,
                              void* d_out, int out_size) {
    (void)in_sizes; (void)n_in; (void)out_size;
    const float* in = (const float*)d_in[0];
    float* out = (float*)d_out;
    fused_kernel<<<NBLOCKS, TPB>>>(in, out);
}

// round 15
// speedup vs baseline: 1.5791x; 1.0059x over previous
#include <cuda_runtime.h>
#include <cuda_bf16.h>

#define QBINS    20
#define NPAIR    11            // packed: 2 bins per 32-bit word (16-bit halves)
#define ROWS     64
#define ROWLEN   1000000
#define ROWLEN4  (ROWLEN / 4)  // 250000 float4 per row
#define BPR      37            // blocks per row -> grid 2368 = 148 * 16 (2 full waves)
#define NBLOCKS  (ROWS * BPR)  // 2368
#define CHUNK4   ((ROWLEN4 + BPR - 1) / BPR)   // 6757
#define TPB      256
#define PITERS   ((CHUNK4 + 4 * TPB - 1) / (4 * TPB))  // 7

__device__ int g_part[ROWS][BPR][QBINS];
__device__ unsigned g_done;    // zero-init at load; last block resets each run

__device__ __forceinline__ int bin_of(float x) {
    // floor(fl_RN(20*x)) bit-exactly: RN(20x)+2^23 is an exact sum; RZ truncates.
    float y = __fadd_rz(__fmul_rn(x, 20.0f), 8388608.0f);  // 2^23
    return __float_as_int(y) - 0x4B000000;
}

// 16-bit packed bump, bank = tid (conflict-free). Max per half-counter:
// 7 iters * 8 bumps = 56 << 65535.
__device__ __forceinline__ void bump(int* h, int bin, int tid) {
    h[(bin >> 1) * TPB + tid] += 1 << ((bin & 1) << 4);
}

__global__ __launch_bounds__(TPB) void fused_kernel(const float* __restrict__ in,
                                                    float* __restrict__ out) {
    __shared__ int hA[NPAIR * TPB];
    __shared__ int hB[NPAIR * TPB];
    __shared__ int wsum[TPB / 32][QBINS];
    __shared__ float psum[TPB / 32];
    __shared__ unsigned s_last;

    const int tid = threadIdx.x;
#pragma unroll
    for (int i = tid; i < NPAIR * TPB; i += TPB) { hA[i] = 0; hB[i] = 0; }
    __syncthreads();

    const int row = blockIdx.x / BPR;
    const int blk = blockIdx.x - row * BPR;
    const int limit = min(CHUNK4, ROWLEN4 - blk * CHUNK4);  // short last chunk
    const float4* __restrict__ p =
        (const float4*)(in + (size_t)row * ROWLEN) + (size_t)blk * CHUNK4;

    for (int k = 0; k < PITERS; k++) {
        const int base = (4 * k) * TPB + tid;
        // Front-batched loads -> 4 LDGs in flight (MLP=4).
        float4 a = make_float4(1.0f, 1.0f, 1.0f, 1.0f);  // sentinel -> bin 20
        float4 b = make_float4(1.0f, 1.0f, 1.0f, 1.0f);
        float4 c = make_float4(1.0f, 1.0f, 1.0f, 1.0f);
        float4 d = make_float4(1.0f, 1.0f, 1.0f, 1.0f);
        if (base            < limit) a = __ldcs(&p[base]);
        if (base +     TPB  < limit) b = __ldcs(&p[base + TPB]);
        if (base + 2 * TPB  < limit) c = __ldcs(&p[base + 2 * TPB]);
        if (base + 3 * TPB  < limit) d = __ldcs(&p[base + 3 * TPB]);

        bump(hA, bin_of(a.x), tid);
        bump(hB, bin_of(a.z), tid);
        bump(hA, bin_of(a.y), tid);
        bump(hB, bin_of(a.w), tid);
        bump(hA, bin_of(b.x), tid);
        bump(hB, bin_of(b.z), tid);
        bump(hA, bin_of(b.y), tid);
        bump(hB, bin_of(b.w), tid);
        bump(hA, bin_of(c.x), tid);
        bump(hB, bin_of(c.z), tid);
        bump(hA, bin_of(c.y), tid);
        bump(hB, bin_of(c.w), tid);
        bump(hA, bin_of(d.x), tid);
        bump(hB, bin_of(d.z), tid);
        bump(hA, bin_of(d.y), tid);
        bump(hB, bin_of(d.w), tid);
    }
    __syncthreads();

    // Block reduction: per bin sum 256 private counters (bank = lane, conflict-free)
    const int wid  = tid >> 5;
    const int lane = tid & 31;
#pragma unroll
    for (int b = 0; b < QBINS; b++) {
        int wA = hA[(b >> 1) * TPB + tid];
        int wB = hB[(b >> 1) * TPB + tid];
        int sh = (b & 1) << 4;
        int v = ((wA >> sh) & 0xFFFF) + ((wB >> sh) & 0xFFFF);
        v = __reduce_add_sync(0xffffffffu, v);
        if (lane == 0) wsum[wid][b] = v;
    }
    __syncthreads();

    if (tid < QBINS) {
        int tot = 0;
#pragma unroll
        for (int w = 0; w < TPB / 32; w++) tot += wsum[w][tid];
        g_part[row][blk][tid] = tot;
    }

    // ---- last-block-done: entropy epilogue in the same launch ----
    __threadfence();
    if (tid == 0) s_last = (atomicAdd(&g_done, 1u) == NBLOCKS - 1u);
    __syncthreads();
    if (!s_last) return;

    if (tid == 0) g_done = 0u;   // reset for next graph replay (determinism)

    // Total loss = sum over all (row,bin) pairs of -p*log2(p).
    // 1280 pairs spread over 256 threads (5 each), 37 partials per pair.
    float ent = 0.0f;
    const float invL = 1.0f / (float)ROWLEN;
#pragma unroll
    for (int q = 0; q < (ROWS * QBINS) / TPB; q++) {
        int pair = q * TPB + tid;           // 0..1279
        int r = pair / QBINS;
        int b = pair - r * QBINS;
        int cnt = 0;
#pragma unroll
        for (int k = 0; k < BPR; k++) cnt += __ldcg(&g_part[r][k][b]);
        if (cnt > 0) {
            float pr = (float)cnt * invL;
            ent -= pr * log2f(pr);
        }
    }
    // block sum
#pragma unroll
    for (int o = 16; o > 0; o >>= 1) ent += __shfl_down_sync(0xffffffffu, ent, o);
    if (lane == 0) psum[wid] = ent;
    __syncthreads();
    if (tid == 0) {
        float s = 0.0f;
#pragma unroll
        for (int w = 0; w < TPB / 32; w++) s += psum[w];
        out[0] = s;
    }
}

extern "C" void kernel_launch(void* const* d_in, const int* in_sizes, int n_in,
                              void* d_out, int out_size) {
    (void)in_sizes; (void)n_in; (void)out_size;
    const float* in = (const float*)d_in[0];
    float* out = (float*)d_out;
    fused_kernel<<<NBLOCKS, TPB>>>(in, out);
}

// round 17
// speedup vs baseline: 1.6288x; 1.0314x over previous
#include <cuda_runtime.h>
#include <cuda_bf16.h>

#define QBINS    20
#define NPAIR    11            // packed: 2 bins per 32-bit word (16-bit halves)
#define ROWS     64
#define ROWLEN   1000000
#define ROWLEN4  (ROWLEN / 4)  // 250000 float4 per row
#define BPR      37            // blocks per row -> grid 2368 = 148 * 16 (2 full waves)
#define NBLOCKS  (ROWS * BPR)  // 2368
#define CHUNK4   ((ROWLEN4 + BPR - 1) / BPR)   // 6757 (last block: 6748)
#define TPB      256
#define NFULL    6             // 6 * 4 * 256 = 6144 <= 6748 (min limit) -> unpredicated
#define TAILB    (NFULL * 4 * TPB)   // 6144; tail covers 3*256 = 768 slots (6912 >= 6757)

__device__ int g_part[ROWS][BPR][QBINS];
__device__ unsigned g_done;    // zero-init at load; last block resets each run

// yi = bits( RN(20x) + 2^23 ) computed with RZ add: low bits hold floor(RN(20x)),
// bit-exact vs the reference's fp32 floor(20*x).
__device__ __forceinline__ unsigned yint_of(float x) {
    return __float_as_uint(__fadd_rz(__fmul_rn(x, 20.0f), 8388608.0f));
}

// Packed bump with folded addressing:
//   byte_off = ((yi & ~1) << 9) + tid*4   (bias*512 == 0 mod 2^32 -> vanishes)
//   incr     = (yi & 1) * 0xFFFF + 1      (1 or 0x10000)
// Max per 16-bit half-counter: (6+1)*8 = 56 << 65535.
__device__ __forceinline__ void bump(int* h, unsigned yi, unsigned tid4) {
    unsigned off = ((yi & ~1u) << 9) + tid4;           // wraps to small value
    int incr = (int)(yi & 1u) * 0xFFFF + 1;
    *(int*)((char*)h + off) += incr;
}

__device__ __forceinline__ void bump16(int* hA, int* hB,
                                       float4 a, float4 b, float4 c, float4 d,
                                       unsigned tid4) {
    bump(hA, yint_of(a.x), tid4); bump(hB, yint_of(a.z), tid4);
    bump(hA, yint_of(a.y), tid4); bump(hB, yint_of(a.w), tid4);
    bump(hA, yint_of(b.x), tid4); bump(hB, yint_of(b.z), tid4);
    bump(hA, yint_of(b.y), tid4); bump(hB, yint_of(b.w), tid4);
    bump(hA, yint_of(c.x), tid4); bump(hB, yint_of(c.z), tid4);
    bump(hA, yint_of(c.y), tid4); bump(hB, yint_of(c.w), tid4);
    bump(hA, yint_of(d.x), tid4); bump(hB, yint_of(d.z), tid4);
    bump(hA, yint_of(d.y), tid4); bump(hB, yint_of(d.w), tid4);
}

__global__ __launch_bounds__(TPB) void fused_kernel(const float* __restrict__ in,
                                                    float* __restrict__ out) {
    __shared__ int hA[NPAIR * TPB];
    __shared__ int hB[NPAIR * TPB];
    __shared__ int wsum[TPB / 32][QBINS];
    __shared__ float psum[TPB / 32];
    __shared__ unsigned s_last;

    const int tid = threadIdx.x;
    const unsigned tid4 = (unsigned)tid * 4u;
#pragma unroll
    for (int i = tid; i < NPAIR * TPB; i += TPB) { hA[i] = 0; hB[i] = 0; }
    __syncthreads();

    const int row = blockIdx.x / BPR;
    const int blk = blockIdx.x - row * BPR;
    const int limit = min(CHUNK4, ROWLEN4 - blk * CHUNK4);  // 6748..6757
    const float4* __restrict__ p =
        (const float4*)(in + (size_t)row * ROWLEN) + (size_t)blk * CHUNK4;

    // ---- main loop: 6 iterations, NO bounds checks (6144 <= min limit) ----
    for (int k = 0; k < NFULL; k++) {
        const int base = (4 * k) * TPB + tid;
        float4 a = __ldcs(&p[base]);
        float4 b = __ldcs(&p[base + TPB]);
        float4 c = __ldcs(&p[base + 2 * TPB]);
        float4 d = __ldcs(&p[base + 3 * TPB]);
        bump16(hA, hB, a, b, c, d, tid4);
    }

    // ---- tail: slots 6144..6911, predicated, sentinels -> bin 20 (trash) ----
    {
        const int base = TAILB + tid;
        float4 a = make_float4(1.0f, 1.0f, 1.0f, 1.0f);
        float4 b = make_float4(1.0f, 1.0f, 1.0f, 1.0f);
        float4 c = make_float4(1.0f, 1.0f, 1.0f, 1.0f);
        if (base           < limit) a = __ldcs(&p[base]);
        if (base + TPB     < limit) b = __ldcs(&p[base + TPB]);
        if (base + 2 * TPB < limit) c = __ldcs(&p[base + 2 * TPB]);
        bump(hA, yint_of(a.x), tid4); bump(hB, yint_of(a.z), tid4);
        bump(hA, yint_of(a.y), tid4); bump(hB, yint_of(a.w), tid4);
        bump(hA, yint_of(b.x), tid4); bump(hB, yint_of(b.z), tid4);
        bump(hA, yint_of(b.y), tid4); bump(hB, yint_of(b.w), tid4);
        bump(hA, yint_of(c.x), tid4); bump(hB, yint_of(c.z), tid4);
        bump(hA, yint_of(c.y), tid4); bump(hB, yint_of(c.w), tid4);
    }
    __syncthreads();

    // Block reduction: per bin sum 256 private counters (bank = lane, conflict-free)
    const int wid  = tid >> 5;
    const int lane = tid & 31;
#pragma unroll
    for (int b = 0; b < QBINS; b++) {
        int wA = hA[(b >> 1) * TPB + tid];
        int wB = hB[(b >> 1) * TPB + tid];
        int sh = (b & 1) << 4;
        int v = ((wA >> sh) & 0xFFFF) + ((wB >> sh) & 0xFFFF);
        v = __reduce_add_sync(0xffffffffu, v);
        if (lane == 0) wsum[wid][b] = v;
    }
    __syncthreads();

    if (tid < QBINS) {
        int tot = 0;
#pragma unroll
        for (int w = 0; w < TPB / 32; w++) tot += wsum[w][tid];
        g_part[row][blk][tid] = tot;
    }

    // ---- last-block-done: entropy epilogue in the same launch ----
    __threadfence();
    if (tid == 0) s_last = (atomicAdd(&g_done, 1u) == NBLOCKS - 1u);
    __syncthreads();
    if (!s_last) return;

    if (tid == 0) g_done = 0u;   // reset for next graph replay (determinism)

    // Total loss = sum over all 1280 (row,bin) pairs of -p*log2(p).
    float ent = 0.0f;
    const float invL = 1.0f / (float)ROWLEN;
#pragma unroll
    for (int q = 0; q < (ROWS * QBINS) / TPB; q++) {
        int pair = q * TPB + tid;           // 0..1279
        int r = pair / QBINS;
        int b = pair - r * QBINS;
        int cnt = 0;
#pragma unroll
        for (int k = 0; k < BPR; k++) cnt += __ldcg(&g_part[r][k][b]);
        if (cnt > 0) {
            float pr = (float)cnt * invL;
            ent -= pr * log2f(pr);
        }
    }
#pragma unroll
    for (int o = 16; o > 0; o >>= 1) ent += __shfl_down_sync(0xffffffffu, ent, o);
    if (lane == 0) psum[wid] = ent;
    __syncthreads();
    if (tid == 0) {
        float s = 0.0f;
#pragma unroll
        for (int w = 0; w < TPB / 32; w++) s += psum[w];
        out[0] = s;
    }
}

extern "C" void kernel_launch(void* const* d_in, const int* in_sizes, int n_in,
                              void* d_out, int out_size) {
    (void)in_sizes; (void)n_in; (void)out_size;
    const float* in = (const float*)d_in[0];
    float* out = (float*)d_out;
    fused_kernel<<<NBLOCKS, TPB>>>(in, out);
}